// round 14
// baseline (speedup 1.0000x reference)
#include <cuda_runtime.h>
#include <cuda_bf16.h>
#include <mma.h>
using namespace nvcuda;

// Problem constants (fixed by the reference setup)
#define MAXN 50000
#define MAXE 800000
#define FEAT 128
#define NHEAD 4
#define CDIM 32
#define NGRAPH 64
#define NEG_SLOPE 0.2f
#define SCAN_BS 256

// ---------------- device scratch (no allocations allowed) ----------------
__device__ __align__(256) __nv_bfloat162 g_xpb[MAXN * (FEAT/2)];  // bf16 features for gather
__device__ __align__(256) float g_asrc[MAXN * NHEAD];     // per-node src logits [N,4]
__device__ __align__(256) float g_adst[MAXN * NHEAD];     // per-node dst logits [N,4]
__device__ __align__(256) float g_ew[MAXE * NHEAD];       // per-edge softmax numerators
__device__ __align__(256) int   g_deg[MAXN];              // in-degree histogram
__device__ __align__(256) int   g_off[MAXN + 1];          // CSR offsets
__device__ __align__(256) int   g_cursor[MAXN];           // CSR fill cursors
__device__ __align__(256) int   g_esrc[MAXE];             // CSR: src node per edge slot
__device__ __align__(256) float g_pooled[NGRAPH * FEAT];  // per-graph feature sums
__device__ __align__(256) int   g_bsum[(MAXN + SCAN_BS - 1) / SCAN_BS];  // block sums
__device__ __align__(256) int   g_bpre[(MAXN + SCAN_BS - 1) / SCAN_BS];  // block prefixes

// ---------------- K0: zero scratch that must start at 0 ----------------
__global__ void zero_kernel(int Nn) {
    int idx = blockIdx.x * blockDim.x + threadIdx.x;
    if (idx < Nn) g_deg[idx] = 0;
    if (idx < NGRAPH * FEAT) g_pooled[idx] = 0.f;
}

// ---------------- K1: xp = x @ W via tf32 tensor cores, fused att dots ----------
__global__ __launch_bounds__(256) void gemm_att_kernel(
    const float* __restrict__ x, const float* __restrict__ W,
    const float* __restrict__ att_s, const float* __restrict__ att_d, int Nn)
{
    __shared__ __align__(16) float sT[64 * 132];   // 33.8KB: x tile, then output tile
    int tid = threadIdx.x;
    int warp = tid >> 5;
    int row0 = blockIdx.x * 64;

    for (int idx = tid; idx < 64 * 32; idx += 256) {
        int r = idx >> 5, c4 = idx & 31;
        float4 v = make_float4(0.f, 0.f, 0.f, 0.f);
        if (row0 + r < Nn) v = ((const float4*)(x + (size_t)(row0 + r) * FEAT))[c4];
        ((float4*)(sT + r * 132))[c4] = v;
    }
    __syncthreads();

    int rt = warp >> 2;      // 0..1 : rows rt*32 .. rt*32+31
    int ct = warp & 3;       // 0..3 : cols ct*32 .. ct*32+31

    wmma::fragment<wmma::accumulator, 16, 16, 8, float> acc[2][2];
#pragma unroll
    for (int i = 0; i < 2; i++)
#pragma unroll
        for (int j = 0; j < 2; j++) wmma::fill_fragment(acc[i][j], 0.0f);

    wmma::fragment<wmma::matrix_a, 16, 16, 8, wmma::precision::tf32, wmma::row_major> fa[2];
    wmma::fragment<wmma::matrix_b, 16, 16, 8, wmma::precision::tf32, wmma::row_major> fb[2];

    for (int k0 = 0; k0 < FEAT; k0 += 8) {
#pragma unroll
        for (int i = 0; i < 2; i++) {
            wmma::load_matrix_sync(fa[i], sT + (rt * 32 + i * 16) * 132 + k0, 132);
#pragma unroll
            for (int t = 0; t < fa[i].num_elements; t++)
                fa[i].x[t] = wmma::__float_to_tf32(fa[i].x[t]);
        }
#pragma unroll
        for (int j = 0; j < 2; j++) {
            wmma::load_matrix_sync(fb[j], W + (size_t)k0 * FEAT + ct * 32 + j * 16, FEAT);
#pragma unroll
            for (int t = 0; t < fb[j].num_elements; t++)
                fb[j].x[t] = wmma::__float_to_tf32(fb[j].x[t]);
        }
#pragma unroll
        for (int i = 0; i < 2; i++)
#pragma unroll
            for (int j = 0; j < 2; j++)
                wmma::mma_sync(acc[i][j], fa[i], fb[j], acc[i][j]);
    }
    __syncthreads();   // all x reads complete before overwriting sT
#pragma unroll
    for (int i = 0; i < 2; i++)
#pragma unroll
        for (int j = 0; j < 2; j++)
            wmma::store_matrix_sync(sT + (rt * 32 + i * 16) * 132 + ct * 32 + j * 16,
                                    acc[i][j], 132, wmma::mem_row_major);
    __syncthreads();

    // bf16 feature write
    for (int idx = tid; idx < 64 * 64; idx += 256) {
        int r = idx >> 6, c2 = idx & 63;
        if (row0 + r < Nn) {
            float lo = sT[r * 132 + c2 * 2];
            float hi = sT[r * 132 + c2 * 2 + 1];
            g_xpb[(size_t)(row0 + r) * (FEAT/2) + c2] = __floats2bfloat162_rn(lo, hi);
        }
    }

    // attention logits in fp32: thread = (row rr, head h)
    {
        int rr = tid >> 2, h = tid & 3;
        if (row0 + rr < Nn) {
            float ds = 0.f, dd = 0.f;
#pragma unroll
            for (int c = 0; c < CDIM; c++) {
                float v = sT[rr * 132 + h * CDIM + c];
                ds += v * att_s[h * CDIM + c];
                dd += v * att_d[h * CDIM + c];
            }
            g_asrc[(row0 + rr) * NHEAD + h] = ds;
            g_adst[(row0 + rr) * NHEAD + h] = dd;
        }
    }
}

// ---------------- K2: in-degree histogram (edge_index is int32) ----------------
__global__ void hist_kernel(const int* __restrict__ ei, int E) {
    int idx = blockIdx.x * blockDim.x + threadIdx.x;
    if (idx < E) atomicAdd(&g_deg[ei[E + idx]], 1);
}

// ---------------- K3a: per-block degree sums ----------------
__global__ __launch_bounds__(SCAN_BS) void scan_pass1(int Nn) {
    __shared__ int sh[SCAN_BS];
    int i = blockIdx.x * SCAN_BS + threadIdx.x;
    int v = (i < Nn) ? g_deg[i] : 0;
    sh[threadIdx.x] = v;
    __syncthreads();
    for (int d = SCAN_BS / 2; d > 0; d >>= 1) {
        if (threadIdx.x < d) sh[threadIdx.x] += sh[threadIdx.x + d];
        __syncthreads();
    }
    if (threadIdx.x == 0) g_bsum[blockIdx.x] = sh[0];
}

// ---------------- K3b: scan of block sums (nb <= 256) ----------------
__global__ __launch_bounds__(SCAN_BS) void scan_pass2(int nb) {
    __shared__ int sh[SCAN_BS];
    int t = threadIdx.x;
    sh[t] = (t < nb) ? g_bsum[t] : 0;
    __syncthreads();
    for (int d = 1; d < SCAN_BS; d <<= 1) {
        int v = (t >= d) ? sh[t - d] : 0;
        __syncthreads();
        sh[t] += v;
        __syncthreads();
    }
    if (t < nb) g_bpre[t] = (t > 0) ? sh[t - 1] : 0;   // exclusive
}

// ---------------- K3c: per-block exclusive scan + offsets + cursors ----------------
__global__ __launch_bounds__(SCAN_BS) void scan_pass3(int Nn) {
    __shared__ int sh[SCAN_BS];
    int t = threadIdx.x;
    int i = blockIdx.x * SCAN_BS + t;
    int v = (i < Nn) ? g_deg[i] : 0;
    sh[t] = v;
    __syncthreads();
    for (int d = 1; d < SCAN_BS; d <<= 1) {
        int u = (t >= d) ? sh[t - d] : 0;
        __syncthreads();
        sh[t] += u;
        __syncthreads();
    }
    int incl = sh[t];
    int base = g_bpre[blockIdx.x];
    int pre = base + incl - v;          // exclusive prefix
    if (i < Nn) {
        g_off[i] = pre;
        g_cursor[i] = pre;
        if (i == Nn - 1) g_off[Nn] = pre + v;
    }
}

// ---------------- K5: CSR fill + edge-weight precompute ----------------
__global__ void csr_kernel(const int* __restrict__ ei, int E) {
    int idx = blockIdx.x * blockDim.x + threadIdx.x;
    if (idx < E) {
        int d = ei[E + idx];
        int s = ei[idx];
        int pos = atomicAdd(&g_cursor[d], 1);
        g_esrc[pos] = s;
        float4 as = *(const float4*)(g_asrc + s * 4);
        float4 ad = *(const float4*)(g_adst + d * 4);
        float f0 = as.x + ad.x, f1 = as.y + ad.y, f2 = as.z + ad.z, f3 = as.w + ad.w;
        float4 w;
        w.x = __expf(fmaxf(f0, NEG_SLOPE * f0));
        w.y = __expf(fmaxf(f1, NEG_SLOPE * f1));
        w.z = __expf(fmaxf(f2, NEG_SLOPE * f2));
        w.w = __expf(fmaxf(f3, NEG_SLOPE * f3));
        *(float4*)(g_ew + (size_t)pos * 4) = w;
    }
}

// ---------------- K6: aggregate + relu + smem-pooled reduction ----------------
// 8 warps/block, 2 dst nodes per warp. Half-warp edge pairing: lane owns 8
// contiguous cols (uint4 of bf16x2); half 0 processes even edges, half 1 odd.
// One LDG.128 covers 2 edges -> warp-LDG per edge halved vs R11. Halves are
// combined with a single xor-16 butterfly per node at the end.
__global__ __launch_bounds__(256) void agg_kernel(
    const int* __restrict__ batch, const float* __restrict__ bias, int Nn)
{
    __shared__ float spool[2][FEAT];
    int tid = threadIdx.x;
    int wIn = tid >> 5;
    int lane = tid & 31;
    int half = lane >> 4;        // 0: even edges, 1: odd edges
    int sl = lane & 15;          // owns cols [sl*8, sl*8+8)
    int h = sl >> 2;             // head of those cols
    int warp = blockIdx.x * 8 + wIn;
    int i0 = warp * 2, i1 = i0 + 1;
    bool has0 = (i0 < Nn), has1 = (i1 < Nn);

    for (int idx = tid; idx < 2 * FEAT; idx += 256) ((float*)spool)[idx] = 0.f;

    int nodeBase = blockIdx.x * 16;
    int gFirst = 0, gLast = 0;
    bool anyNode = (nodeBase < Nn);
    if (anyNode) {
        gFirst = batch[nodeBase];
        gLast  = batch[min(nodeBase + 15, Nn - 1)];
    }
    bool smemOK = anyNode && (gLast - gFirst <= 1);
    __syncthreads();

    float a0[8], a1[8];
#pragma unroll
    for (int k = 0; k < 8; k++) { a0[k] = 0.f; a1[k] = 0.f; }
    float s0 = 0.f, s1 = 0.f, ws0 = 0.f, ws1 = 0.f;

    if (has0) {
        float es = g_asrc[i0 * 4 + h] + g_adst[i0 * 4 + h];
        ws0 = __expf(fmaxf(es, NEG_SLOPE * es));
        if (half == 0) {       // self contribution counted once (half 0)
            uint4 u = ((const uint4*)(g_xpb + (size_t)i0 * (FEAT/2)))[sl];
            float2 f0 = __bfloat1622float2(*reinterpret_cast<__nv_bfloat162*>(&u.x));
            float2 f1 = __bfloat1622float2(*reinterpret_cast<__nv_bfloat162*>(&u.y));
            float2 f2 = __bfloat1622float2(*reinterpret_cast<__nv_bfloat162*>(&u.z));
            float2 f3 = __bfloat1622float2(*reinterpret_cast<__nv_bfloat162*>(&u.w));
            a0[0] = ws0 * f0.x; a0[1] = ws0 * f0.y; a0[2] = ws0 * f1.x; a0[3] = ws0 * f1.y;
            a0[4] = ws0 * f2.x; a0[5] = ws0 * f2.y; a0[6] = ws0 * f3.x; a0[7] = ws0 * f3.y;
        }
    }
    if (has1) {
        float es = g_asrc[i1 * 4 + h] + g_adst[i1 * 4 + h];
        ws1 = __expf(fmaxf(es, NEG_SLOPE * es));
        if (half == 0) {
            uint4 u = ((const uint4*)(g_xpb + (size_t)i1 * (FEAT/2)))[sl];
            float2 f0 = __bfloat1622float2(*reinterpret_cast<__nv_bfloat162*>(&u.x));
            float2 f1 = __bfloat1622float2(*reinterpret_cast<__nv_bfloat162*>(&u.y));
            float2 f2 = __bfloat1622float2(*reinterpret_cast<__nv_bfloat162*>(&u.z));
            float2 f3 = __bfloat1622float2(*reinterpret_cast<__nv_bfloat162*>(&u.w));
            a1[0] = ws1 * f0.x; a1[1] = ws1 * f0.y; a1[2] = ws1 * f1.x; a1[3] = ws1 * f1.y;
            a1[4] = ws1 * f2.x; a1[5] = ws1 * f2.y; a1[6] = ws1 * f3.x; a1[7] = ws1 * f3.y;
        }
    }

    int beg0 = has0 ? g_off[i0] : 0, end0 = has0 ? g_off[i0 + 1] : 0;
    int beg1 = has1 ? g_off[i1] : 0, end1 = has1 ? g_off[i1 + 1] : 0;
    int len0 = end0 - beg0, len1 = end1 - beg1;
    int L = max((len0 + 1) >> 1, (len1 + 1) >> 1);

#pragma unroll 2
    for (int t = 0; t < L; t++) {
        int e = 2 * t + half;
        bool p0 = has0 && (e < len0);
        bool p1 = has1 && (e < len1);
        int sj0 = p0 ? g_esrc[beg0 + e] : 0;
        int sj1 = p1 ? g_esrc[beg1 + e] : 0;
        float w0 = p0 ? g_ew[(size_t)(beg0 + e) * 4 + h] : 0.f;
        float w1 = p1 ? g_ew[(size_t)(beg1 + e) * 4 + h] : 0.f;
        if (p0) {
            uint4 u = ((const uint4*)(g_xpb + (size_t)sj0 * (FEAT/2)))[sl];
            float2 f0 = __bfloat1622float2(*reinterpret_cast<__nv_bfloat162*>(&u.x));
            float2 f1 = __bfloat1622float2(*reinterpret_cast<__nv_bfloat162*>(&u.y));
            float2 f2 = __bfloat1622float2(*reinterpret_cast<__nv_bfloat162*>(&u.z));
            float2 f3 = __bfloat1622float2(*reinterpret_cast<__nv_bfloat162*>(&u.w));
            s0 += w0;
            a0[0] += w0 * f0.x; a0[1] += w0 * f0.y; a0[2] += w0 * f1.x; a0[3] += w0 * f1.y;
            a0[4] += w0 * f2.x; a0[5] += w0 * f2.y; a0[6] += w0 * f3.x; a0[7] += w0 * f3.y;
        }
        if (p1) {
            uint4 u = ((const uint4*)(g_xpb + (size_t)sj1 * (FEAT/2)))[sl];
            float2 f0 = __bfloat1622float2(*reinterpret_cast<__nv_bfloat162*>(&u.x));
            float2 f1 = __bfloat1622float2(*reinterpret_cast<__nv_bfloat162*>(&u.y));
            float2 f2 = __bfloat1622float2(*reinterpret_cast<__nv_bfloat162*>(&u.z));
            float2 f3 = __bfloat1622float2(*reinterpret_cast<__nv_bfloat162*>(&u.w));
            s1 += w1;
            a1[0] += w1 * f0.x; a1[1] += w1 * f0.y; a1[2] += w1 * f1.x; a1[3] += w1 * f1.y;
            a1[4] += w1 * f2.x; a1[5] += w1 * f2.y; a1[6] += w1 * f3.x; a1[7] += w1 * f3.y;
        }
    }

    // combine even/odd halves (ws identical in both halves -> add once after)
    s0 += __shfl_xor_sync(0xffffffffu, s0, 16);
    s1 += __shfl_xor_sync(0xffffffffu, s1, 16);
#pragma unroll
    for (int k = 0; k < 8; k++) {
        a0[k] += __shfl_xor_sync(0xffffffffu, a0[k], 16);
        a1[k] += __shfl_xor_sync(0xffffffffu, a1[k], 16);
    }
    s0 += ws0;
    s1 += ws1;

    float4 bA = ((const float4*)bias)[sl * 2];
    float4 bB = ((const float4*)bias)[sl * 2 + 1];
    float bb[8] = {bA.x, bA.y, bA.z, bA.w, bB.x, bB.y, bB.z, bB.w};

    if (half == 0 && has0) {
        float inv = 1.0f / s0;
        int g = batch[i0];
        float* dst = smemOK ? (spool[g - gFirst] + sl * 8)
                            : (g_pooled + g * FEAT + sl * 8);
#pragma unroll
        for (int k = 0; k < 8; k++)
            atomicAdd(dst + k, fmaxf(a0[k] * inv + bb[k], 0.f));
    }
    if (half == 0 && has1) {
        float inv = 1.0f / s1;
        int g = batch[i1];
        float* dst = smemOK ? (spool[g - gFirst] + sl * 8)
                            : (g_pooled + g * FEAT + sl * 8);
#pragma unroll
        for (int k = 0; k < 8; k++)
            atomicAdd(dst + k, fmaxf(a1[k] * inv + bb[k], 0.f));
    }

    __syncthreads();
    if (smemOK) {
        for (int idx = tid; idx < 2 * FEAT; idx += 256) {
            int bank = idx >> 7, c = idx & 127;
            float v = ((float*)spool)[idx];
            int g = gFirst + bank;
            if (v != 0.f && g < NGRAPH)
                atomicAdd(&g_pooled[g * FEAT + c], v);
        }
    }
}

// ---------------- K7: mean + final linear ----------------
__global__ void final_kernel(const int* __restrict__ batch, int Nn,
                             const float* __restrict__ Wl, const float* __restrict__ bl,
                             float* __restrict__ out)
{
    int t = threadIdx.x;
    if (t >= NGRAPH * 2) return;
    int g = t >> 1, o = t & 1;
    int lo = 0, hi = Nn;
    while (lo < hi) { int m = (lo + hi) >> 1; if (batch[m] < g) lo = m + 1; else hi = m; }
    int c0 = lo;
    lo = 0; hi = Nn;
    while (lo < hi) { int m = (lo + hi) >> 1; if (batch[m] < g + 1) lo = m + 1; else hi = m; }
    int cnt = lo - c0;
    float fc = (float)max(cnt, 1);
    float sum = 0.f;
#pragma unroll 4
    for (int k = 0; k < FEAT; k++) sum += g_pooled[g * FEAT + k] * Wl[k * 2 + o];
    out[g * 2 + o] = sum / fc + bl[o];
}

// ---------------- launch ----------------
extern "C" void kernel_launch(void* const* d_in, const int* in_sizes, int n_in,
                              void* d_out, int out_size)
{
    const float* x     = (const float*)d_in[0];
    const int*   ei    = (const int*)d_in[1];     // int32 on the wire
    const int*   batch = (const int*)d_in[2];     // int32 on the wire
    const float* W     = (const float*)d_in[3];
    const float* att_s = (const float*)d_in[4];
    const float* att_d = (const float*)d_in[5];
    const float* bias  = (const float*)d_in[6];
    const float* Wl    = (const float*)d_in[7];
    const float* bl    = (const float*)d_in[8];
    float* out = (float*)d_out;

    int N = in_sizes[0] / FEAT;
    int E = in_sizes[1] / 2;
    int nb = (N + SCAN_BS - 1) / SCAN_BS;

    zero_kernel<<<(N + 255) / 256, 256>>>(N);
    gemm_att_kernel<<<(N + 63) / 64, 256>>>(x, W, att_s, att_d, N);
    hist_kernel<<<(E + 255) / 256, 256>>>(ei, E);
    scan_pass1<<<nb, SCAN_BS>>>(N);
    scan_pass2<<<1, SCAN_BS>>>(nb);
    scan_pass3<<<nb, SCAN_BS>>>(N);
    csr_kernel<<<(E + 255) / 256, 256>>>(ei, E);
    {
        int nblocks = (N + 15) / 16;    // 16 nodes per block (8 warps x 2)
        agg_kernel<<<nblocks, 256>>>(batch, bias, N);
    }
    final_kernel<<<1, 128>>>(batch, N, Wl, bl, out);
}

// round 15
// speedup vs baseline: 1.1390x; 1.1390x over previous
#include <cuda_runtime.h>
#include <cuda_bf16.h>
#include <mma.h>
using namespace nvcuda;

// Problem constants (fixed by the reference setup)
#define MAXN 50000
#define MAXE 800000
#define FEAT 128
#define NHEAD 4
#define CDIM 32
#define NGRAPH 64
#define NEG_SLOPE 0.2f
#define SCAN_BS 256

// ---------------- device scratch (no allocations allowed) ----------------
__device__ __align__(256) __nv_bfloat162 g_xpb[MAXN * (FEAT/2)];  // bf16 features for gather
__device__ __align__(256) float g_asrc[MAXN * NHEAD];     // per-node src logits [N,4]
__device__ __align__(256) float g_adst[MAXN * NHEAD];     // per-node dst logits [N,4]
__device__ __align__(256) uint4 g_epack[MAXE];            // {src, ew01 bf16x2, ew23 bf16x2, pad}
__device__ __align__(256) int   g_deg[MAXN];              // in-degree histogram
__device__ __align__(256) int   g_off[MAXN + 1];          // CSR offsets
__device__ __align__(256) int   g_cursor[MAXN];           // CSR fill cursors
__device__ __align__(256) float g_pooled[NGRAPH * FEAT];  // per-graph feature sums
__device__ __align__(256) int   g_bsum[(MAXN + SCAN_BS - 1) / SCAN_BS];  // block sums

// ---------------- K1: xp = x @ W via tf32 tensor cores, fused att dots ----------
// Also zeroes g_deg (runs before hist).
__global__ __launch_bounds__(256) void gemm_att_kernel(
    const float* __restrict__ x, const float* __restrict__ W,
    const float* __restrict__ att_s, const float* __restrict__ att_d, int Nn)
{
    __shared__ __align__(16) float sT[64 * 132];   // 33.8KB: x tile, then output tile
    int tid = threadIdx.x;
    int warp = tid >> 5;
    int row0 = blockIdx.x * 64;

    // zero g_deg (grid covers N: (N+63)/64 blocks x 256 >= N)
    {
        int gid = blockIdx.x * 256 + tid;
        if (gid < Nn) g_deg[gid] = 0;
    }

    for (int idx = tid; idx < 64 * 32; idx += 256) {
        int r = idx >> 5, c4 = idx & 31;
        float4 v = make_float4(0.f, 0.f, 0.f, 0.f);
        if (row0 + r < Nn) v = ((const float4*)(x + (size_t)(row0 + r) * FEAT))[c4];
        ((float4*)(sT + r * 132))[c4] = v;
    }
    __syncthreads();

    int rt = warp >> 2;      // 0..1 : rows rt*32 .. rt*32+31
    int ct = warp & 3;       // 0..3 : cols ct*32 .. ct*32+31

    wmma::fragment<wmma::accumulator, 16, 16, 8, float> acc[2][2];
#pragma unroll
    for (int i = 0; i < 2; i++)
#pragma unroll
        for (int j = 0; j < 2; j++) wmma::fill_fragment(acc[i][j], 0.0f);

    wmma::fragment<wmma::matrix_a, 16, 16, 8, wmma::precision::tf32, wmma::row_major> fa[2];
    wmma::fragment<wmma::matrix_b, 16, 16, 8, wmma::precision::tf32, wmma::row_major> fb[2];

    for (int k0 = 0; k0 < FEAT; k0 += 8) {
#pragma unroll
        for (int i = 0; i < 2; i++) {
            wmma::load_matrix_sync(fa[i], sT + (rt * 32 + i * 16) * 132 + k0, 132);
#pragma unroll
            for (int t = 0; t < fa[i].num_elements; t++)
                fa[i].x[t] = wmma::__float_to_tf32(fa[i].x[t]);
        }
#pragma unroll
        for (int j = 0; j < 2; j++) {
            wmma::load_matrix_sync(fb[j], W + (size_t)k0 * FEAT + ct * 32 + j * 16, FEAT);
#pragma unroll
            for (int t = 0; t < fb[j].num_elements; t++)
                fb[j].x[t] = wmma::__float_to_tf32(fb[j].x[t]);
        }
#pragma unroll
        for (int i = 0; i < 2; i++)
#pragma unroll
            for (int j = 0; j < 2; j++)
                wmma::mma_sync(acc[i][j], fa[i], fb[j], acc[i][j]);
    }
    __syncthreads();   // all x reads complete before overwriting sT
#pragma unroll
    for (int i = 0; i < 2; i++)
#pragma unroll
        for (int j = 0; j < 2; j++)
            wmma::store_matrix_sync(sT + (rt * 32 + i * 16) * 132 + ct * 32 + j * 16,
                                    acc[i][j], 132, wmma::mem_row_major);
    __syncthreads();

    // bf16 feature write
    for (int idx = tid; idx < 64 * 64; idx += 256) {
        int r = idx >> 6, c2 = idx & 63;
        if (row0 + r < Nn) {
            float lo = sT[r * 132 + c2 * 2];
            float hi = sT[r * 132 + c2 * 2 + 1];
            g_xpb[(size_t)(row0 + r) * (FEAT/2) + c2] = __floats2bfloat162_rn(lo, hi);
        }
    }

    // attention logits in fp32: thread = (row rr, head h)
    {
        int rr = tid >> 2, h = tid & 3;
        if (row0 + rr < Nn) {
            float ds = 0.f, dd = 0.f;
#pragma unroll
            for (int c = 0; c < CDIM; c++) {
                float v = sT[rr * 132 + h * CDIM + c];
                ds += v * att_s[h * CDIM + c];
                dd += v * att_d[h * CDIM + c];
            }
            g_asrc[(row0 + rr) * NHEAD + h] = ds;
            g_adst[(row0 + rr) * NHEAD + h] = dd;
        }
    }
}

// ---------------- K2: in-degree histogram (edge_index is int32) ----------------
__global__ void hist_kernel(const int* __restrict__ ei, int E) {
    int idx = blockIdx.x * blockDim.x + threadIdx.x;
    if (idx < E) atomicAdd(&g_deg[ei[E + idx]], 1);
}

// ---------------- K3a: per-block degree sums (+ zero g_pooled) ----------------
__global__ __launch_bounds__(SCAN_BS) void scan_pass1(int Nn) {
    __shared__ int sh[SCAN_BS];
    int i = blockIdx.x * SCAN_BS + threadIdx.x;
    if (i < NGRAPH * FEAT) g_pooled[i] = 0.f;      // ride-along zero (before agg)
    int v = (i < Nn) ? g_deg[i] : 0;
    sh[threadIdx.x] = v;
    __syncthreads();
    for (int d = SCAN_BS / 2; d > 0; d >>= 1) {
        if (threadIdx.x < d) sh[threadIdx.x] += sh[threadIdx.x + d];
        __syncthreads();
    }
    if (threadIdx.x == 0) g_bsum[blockIdx.x] = sh[0];
}

// ---------------- K3b: per-block scan + offsets + cursors (base computed locally) --
__global__ __launch_bounds__(SCAN_BS) void scan_pass3(int Nn, int nb) {
    __shared__ int sb[SCAN_BS];
    __shared__ int sh[SCAN_BS];
    int t = threadIdx.x;

    // base = sum of block sums before this block (nb <= 256 always for MAXN)
    sb[t] = (t < nb && t < (int)blockIdx.x) ? g_bsum[t] : 0;
    __syncthreads();
    for (int d = SCAN_BS / 2; d > 0; d >>= 1) {
        if (t < d) sb[t] += sb[t + d];
        __syncthreads();
    }
    int base = sb[0];

    int i = blockIdx.x * SCAN_BS + t;
    int v = (i < Nn) ? g_deg[i] : 0;
    sh[t] = v;
    __syncthreads();
    for (int d = 1; d < SCAN_BS; d <<= 1) {
        int u = (t >= d) ? sh[t - d] : 0;
        __syncthreads();
        sh[t] += u;
        __syncthreads();
    }
    int incl = sh[t];
    int pre = base + incl - v;          // exclusive prefix
    if (i < Nn) {
        g_off[i] = pre;
        g_cursor[i] = pre;
        if (i == Nn - 1) g_off[Nn] = pre + v;
    }
}

// ---------------- K5: CSR fill + packed edge record ----------------
// record = {src:int, ew[0..1]:bf16x2, ew[2..3]:bf16x2, pad}
__global__ void csr_kernel(const int* __restrict__ ei, int E) {
    int idx = blockIdx.x * blockDim.x + threadIdx.x;
    if (idx < E) {
        int d = ei[E + idx];
        int s = ei[idx];
        int pos = atomicAdd(&g_cursor[d], 1);
        float4 as = *(const float4*)(g_asrc + s * 4);
        float4 ad = *(const float4*)(g_adst + d * 4);
        float f0 = as.x + ad.x, f1 = as.y + ad.y, f2 = as.z + ad.z, f3 = as.w + ad.w;
        float w0 = __expf(fmaxf(f0, NEG_SLOPE * f0));
        float w1 = __expf(fmaxf(f1, NEG_SLOPE * f1));
        float w2 = __expf(fmaxf(f2, NEG_SLOPE * f2));
        float w3 = __expf(fmaxf(f3, NEG_SLOPE * f3));
        __nv_bfloat162 p01 = __floats2bfloat162_rn(w0, w1);
        __nv_bfloat162 p23 = __floats2bfloat162_rn(w2, w3);
        uint4 r;
        r.x = (unsigned)s;
        r.y = *reinterpret_cast<unsigned*>(&p01);
        r.z = *reinterpret_cast<unsigned*>(&p23);
        r.w = 0;
        g_epack[pos] = r;
    }
}

// ---------------- K6: aggregate + relu + smem-pooled reduction ----------------
// R11-proven structure: 8 warps/block, 2 dst nodes per warp, lane owns 4 cols.
// Only change vs R11: esrc+ew come from ONE packed 16B load per edge.
__global__ __launch_bounds__(256) void agg_kernel(
    const int* __restrict__ batch, const float* __restrict__ bias, int Nn)
{
    __shared__ float spool[2][FEAT];
    int tid = threadIdx.x;
    int wIn = tid >> 5;
    int lane = tid & 31;
    int warp = blockIdx.x * 8 + wIn;
    int i0 = warp * 2;
    int i1 = i0 + 1;
    bool has0 = (i0 < Nn);
    bool has1 = (i1 < Nn);
    int h = lane >> 3;           // head of my 4 columns

    for (int idx = tid; idx < 2 * FEAT; idx += 256) ((float*)spool)[idx] = 0.f;

    int nodeBase = blockIdx.x * 16;
    int gFirst = 0, gLast = 0;
    bool anyNode = (nodeBase < Nn);
    if (anyNode) {
        gFirst = batch[nodeBase];
        gLast  = batch[min(nodeBase + 15, Nn - 1)];
    }
    bool smemOK = anyNode && (gLast - gFirst <= 1);
    __syncthreads();

    float4 acc0 = make_float4(0.f, 0.f, 0.f, 0.f);
    float4 acc1 = make_float4(0.f, 0.f, 0.f, 0.f);
    float s0 = 0.f, s1 = 0.f;

    if (has0) {
        float adh = g_adst[i0 * 4 + h];
        float es = g_asrc[i0 * 4 + h] + adh;
        float ws = __expf(fmaxf(es, NEG_SLOPE * es));
        uint2 u = ((const uint2*)(g_xpb + (size_t)i0 * (FEAT/2)))[lane];
        float2 p0 = __bfloat1622float2(*reinterpret_cast<__nv_bfloat162*>(&u.x));
        float2 p1 = __bfloat1622float2(*reinterpret_cast<__nv_bfloat162*>(&u.y));
        acc0 = make_float4(ws * p0.x, ws * p0.y, ws * p1.x, ws * p1.y);
        s0 = ws;
    }
    if (has1) {
        float adh = g_adst[i1 * 4 + h];
        float es = g_asrc[i1 * 4 + h] + adh;
        float ws = __expf(fmaxf(es, NEG_SLOPE * es));
        uint2 u = ((const uint2*)(g_xpb + (size_t)i1 * (FEAT/2)))[lane];
        float2 p0 = __bfloat1622float2(*reinterpret_cast<__nv_bfloat162*>(&u.x));
        float2 p1 = __bfloat1622float2(*reinterpret_cast<__nv_bfloat162*>(&u.y));
        acc1 = make_float4(ws * p0.x, ws * p0.y, ws * p1.x, ws * p1.y);
        s1 = ws;
    }

    int beg0 = has0 ? g_off[i0] : 0, end0 = has0 ? g_off[i0 + 1] : 0;
    int beg1 = has1 ? g_off[i1] : 0, end1 = has1 ? g_off[i1 + 1] : 0;
    int len0 = end0 - beg0, len1 = end1 - beg1;
    int L = max(len0, len1);

#pragma unroll 2
    for (int t = 0; t < L; t++) {
        uint4 pk0 = make_uint4(0, 0, 0, 0);
        uint4 pk1 = make_uint4(0, 0, 0, 0);
        if (t < len0) pk0 = g_epack[beg0 + t];
        if (t < len1) pk1 = g_epack[beg1 + t];
        if (t < len0) {
            unsigned wb = (h < 2) ? pk0.y : pk0.z;
            float2 wp = __bfloat1622float2(*reinterpret_cast<__nv_bfloat162*>(&wb));
            float w = (h & 1) ? wp.y : wp.x;
            s0 += w;
            uint2 u = ((const uint2*)(g_xpb + (size_t)pk0.x * (FEAT/2)))[lane];
            float2 p0 = __bfloat1622float2(*reinterpret_cast<__nv_bfloat162*>(&u.x));
            float2 p1 = __bfloat1622float2(*reinterpret_cast<__nv_bfloat162*>(&u.y));
            acc0.x += w * p0.x; acc0.y += w * p0.y; acc0.z += w * p1.x; acc0.w += w * p1.y;
        }
        if (t < len1) {
            unsigned wb = (h < 2) ? pk1.y : pk1.z;
            float2 wp = __bfloat1622float2(*reinterpret_cast<__nv_bfloat162*>(&wb));
            float w = (h & 1) ? wp.y : wp.x;
            s1 += w;
            uint2 u = ((const uint2*)(g_xpb + (size_t)pk1.x * (FEAT/2)))[lane];
            float2 p0 = __bfloat1622float2(*reinterpret_cast<__nv_bfloat162*>(&u.x));
            float2 p1 = __bfloat1622float2(*reinterpret_cast<__nv_bfloat162*>(&u.y));
            acc1.x += w * p0.x; acc1.y += w * p0.y; acc1.z += w * p1.x; acc1.w += w * p1.y;
        }
    }

    float4 b4 = ((const float4*)bias)[lane];

    if (has0) {
        float inv = 1.0f / s0;
        float o0 = fmaxf(acc0.x * inv + b4.x, 0.f);
        float o1 = fmaxf(acc0.y * inv + b4.y, 0.f);
        float o2 = fmaxf(acc0.z * inv + b4.z, 0.f);
        float o3 = fmaxf(acc0.w * inv + b4.w, 0.f);
        int g = batch[i0];
        if (smemOK) {
            float* sp = spool[g - gFirst] + lane * 4;
            atomicAdd(sp + 0, o0); atomicAdd(sp + 1, o1);
            atomicAdd(sp + 2, o2); atomicAdd(sp + 3, o3);
        } else {
            float* pg = g_pooled + g * FEAT + lane * 4;
            atomicAdd(pg + 0, o0); atomicAdd(pg + 1, o1);
            atomicAdd(pg + 2, o2); atomicAdd(pg + 3, o3);
        }
    }
    if (has1) {
        float inv = 1.0f / s1;
        float o0 = fmaxf(acc1.x * inv + b4.x, 0.f);
        float o1 = fmaxf(acc1.y * inv + b4.y, 0.f);
        float o2 = fmaxf(acc1.z * inv + b4.z, 0.f);
        float o3 = fmaxf(acc1.w * inv + b4.w, 0.f);
        int g = batch[i1];
        if (smemOK) {
            float* sp = spool[g - gFirst] + lane * 4;
            atomicAdd(sp + 0, o0); atomicAdd(sp + 1, o1);
            atomicAdd(sp + 2, o2); atomicAdd(sp + 3, o3);
        } else {
            float* pg = g_pooled + g * FEAT + lane * 4;
            atomicAdd(pg + 0, o0); atomicAdd(pg + 1, o1);
            atomicAdd(pg + 2, o2); atomicAdd(pg + 3, o3);
        }
    }

    __syncthreads();
    if (smemOK) {
        for (int idx = tid; idx < 2 * FEAT; idx += 256) {
            int bank = idx >> 7, c = idx & 127;
            float v = ((float*)spool)[idx];
            int g = gFirst + bank;
            if (v != 0.f && g < NGRAPH)
                atomicAdd(&g_pooled[g * FEAT + c], v);
        }
    }
}

// ---------------- K7: mean + final linear ----------------
__global__ void final_kernel(const int* __restrict__ batch, int Nn,
                             const float* __restrict__ Wl, const float* __restrict__ bl,
                             float* __restrict__ out)
{
    int t = threadIdx.x;
    if (t >= NGRAPH * 2) return;
    int g = t >> 1, o = t & 1;
    int lo = 0, hi = Nn;
    while (lo < hi) { int m = (lo + hi) >> 1; if (batch[m] < g) lo = m + 1; else hi = m; }
    int c0 = lo;
    lo = 0; hi = Nn;
    while (lo < hi) { int m = (lo + hi) >> 1; if (batch[m] < g + 1) lo = m + 1; else hi = m; }
    int cnt = lo - c0;
    float fc = (float)max(cnt, 1);
    float sum = 0.f;
#pragma unroll 4
    for (int k = 0; k < FEAT; k++) sum += g_pooled[g * FEAT + k] * Wl[k * 2 + o];
    out[g * 2 + o] = sum / fc + bl[o];
}

// ---------------- launch ----------------
extern "C" void kernel_launch(void* const* d_in, const int* in_sizes, int n_in,
                              void* d_out, int out_size)
{
    const float* x     = (const float*)d_in[0];
    const int*   ei    = (const int*)d_in[1];     // int32 on the wire
    const int*   batch = (const int*)d_in[2];     // int32 on the wire
    const float* W     = (const float*)d_in[3];
    const float* att_s = (const float*)d_in[4];
    const float* att_d = (const float*)d_in[5];
    const float* bias  = (const float*)d_in[6];
    const float* Wl    = (const float*)d_in[7];
    const float* bl    = (const float*)d_in[8];
    float* out = (float*)d_out;

    int N = in_sizes[0] / FEAT;
    int E = in_sizes[1] / 2;
    int nb = (N + SCAN_BS - 1) / SCAN_BS;

    gemm_att_kernel<<<(N + 63) / 64, 256>>>(x, W, att_s, att_d, N);   // also zeroes g_deg
    hist_kernel<<<(E + 255) / 256, 256>>>(ei, E);
    scan_pass1<<<nb, SCAN_BS>>>(N);                                   // also zeroes g_pooled
    scan_pass3<<<nb, SCAN_BS>>>(N, nb);
    csr_kernel<<<(E + 255) / 256, 256>>>(ei, E);
    {
        int nblocks = (N + 15) / 16;    // 16 nodes per block (8 warps x 2)
        agg_kernel<<<nblocks, 256>>>(batch, bias, N);
    }
    final_kernel<<<1, 128>>>(batch, N, Wl, bl, out);
}